// round 2
// baseline (speedup 1.0000x reference)
#include <cuda_runtime.h>
#include <cuda_bf16.h>

// ---------------------------------------------------------------------------
// MultiHeadAttention_31799937859897 — Round 1 baseline
//
// Structure:
//   1) gemm_nt_bias  x3 : Q/K/V projections  (16384x1024)@(1024x1024)^T + bias
//   2) attn_ln          : per-token 16x16 head-mix softmax + LayerNorm (fused)
//   3) gemm_nt_bias     : output projection -> d_out
//
// GEMM microkernel uses packed fma.rn.f32x2 (sm_103a) for 2x fp32 FMA rate.
// Scratch via __device__ globals (no allocation).
// ---------------------------------------------------------------------------

#define M_TOK   16384          // BATCH*SEQ = 8*2048
#define DMODEL  1024

__device__ float g_q[M_TOK * DMODEL];
__device__ float g_k[M_TOK * DMODEL];
__device__ float g_v[M_TOK * DMODEL];
__device__ float g_x[M_TOK * DMODEL];

typedef unsigned long long ull;

__device__ __forceinline__ void ffma2(ull& c, ull a, ull b) {
    asm("fma.rn.f32x2 %0, %1, %2, %0;" : "+l"(c) : "l"(a), "l"(b));
}
__device__ __forceinline__ ull packdup(float x) {
    ull r; unsigned xi = __float_as_uint(x);
    asm("mov.b64 %0, {%1, %2};" : "=l"(r) : "r"(xi), "r"(xi));
    return r;
}
__device__ __forceinline__ void unpack2(ull c, float& lo, float& hi) {
    asm("mov.b64 {%0, %1}, %2;" : "=f"(lo), "=f"(hi) : "l"(c));
}

// C[m,n] = sum_k A[m,k]*B[n,k] + bias[n]
// A: MxK row-major, B: NxK row-major (i.e. C = A @ B^T + bias)
// Tile: 128x128x8, 256 threads, 8x8 per thread, f32x2 packed accumulators.
__global__ __launch_bounds__(256, 2)
void gemm_nt_bias(const float* __restrict__ A, const float* __restrict__ B,
                  const float* __restrict__ bias, float* __restrict__ C,
                  int M, int N, int K)
{
    __shared__ float As[8][128];
    __shared__ float Bs[8][128];

    const int tid = threadIdx.x;
    const int tx  = tid & 15;       // 0..15  -> col group
    const int ty  = tid >> 4;       // 0..15  -> row group
    const int r   = tid >> 1;       // 0..127 -> load row
    const int kc  = (tid & 1) * 4;  // 0 or 4 -> load k offset

    const float* Ap = A + (size_t)(blockIdx.y * 128 + r) * K + kc;
    const float* Bp = B + (size_t)(blockIdx.x * 128 + r) * K + kc;

    ull c2[8][4];
    #pragma unroll
    for (int i = 0; i < 8; i++)
        #pragma unroll
        for (int j = 0; j < 4; j++)
            c2[i][j] = 0ull;   // bit pattern (0.0f, 0.0f)

    float4 a4 = *(const float4*)Ap;
    float4 b4 = *(const float4*)Bp;

    for (int k0 = 0; k0 < K; k0 += 8) {
        As[kc + 0][r] = a4.x; As[kc + 1][r] = a4.y;
        As[kc + 2][r] = a4.z; As[kc + 3][r] = a4.w;
        Bs[kc + 0][r] = b4.x; Bs[kc + 1][r] = b4.y;
        Bs[kc + 2][r] = b4.z; Bs[kc + 3][r] = b4.w;
        __syncthreads();

        Ap += 8; Bp += 8;
        const bool more = (k0 + 8) < K;
        if (more) {
            a4 = *(const float4*)Ap;
            b4 = *(const float4*)Bp;
        }

        #pragma unroll
        for (int kk = 0; kk < 8; kk++) {
            const float4 alo = *(const float4*)&As[kk][ty * 8];
            const float4 ahi = *(const float4*)&As[kk][ty * 8 + 4];
            const ulonglong2 bb0 = *(const ulonglong2*)&Bs[kk][tx * 8];
            const ulonglong2 bb1 = *(const ulonglong2*)&Bs[kk][tx * 8 + 4];

            ull av[8];
            av[0] = packdup(alo.x); av[1] = packdup(alo.y);
            av[2] = packdup(alo.z); av[3] = packdup(alo.w);
            av[4] = packdup(ahi.x); av[5] = packdup(ahi.y);
            av[6] = packdup(ahi.z); av[7] = packdup(ahi.w);
            ull bv[4] = { bb0.x, bb0.y, bb1.x, bb1.y };

            #pragma unroll
            for (int i = 0; i < 8; i++)
                #pragma unroll
                for (int j = 0; j < 4; j++)
                    ffma2(c2[i][j], av[i], bv[j]);
        }
        __syncthreads();
    }

    const int row0 = blockIdx.y * 128 + ty * 8;
    const int col0 = blockIdx.x * 128 + tx * 8;
    float bvals[8];
    #pragma unroll
    for (int j = 0; j < 8; j++) bvals[j] = bias[col0 + j];

    #pragma unroll
    for (int i = 0; i < 8; i++) {
        float o[8];
        #pragma unroll
        for (int j = 0; j < 4; j++) {
            float lo, hi;
            unpack2(c2[i][j], lo, hi);
            o[2 * j]     = lo + bvals[2 * j];
            o[2 * j + 1] = hi + bvals[2 * j + 1];
        }
        float4 v0 = make_float4(o[0], o[1], o[2], o[3]);
        float4 v1 = make_float4(o[4], o[5], o[6], o[7]);
        *(float4*)&C[(size_t)(row0 + i) * N + col0]     = v0;
        *(float4*)&C[(size_t)(row0 + i) * N + col0 + 4] = v1;
    }
}

// Per-token head-to-head attention + LayerNorm, one block per token.
//   energy[h,g] = sum_d q[h,d] k[g,d];  attn = softmax_g(energy/32)
//   out[h,d]    = sum_g attn[h,g] v[g,d];  then LN over 1024 dims.
__global__ __launch_bounds__(256)
void attn_ln(const float* __restrict__ Q, const float* __restrict__ Kp,
             const float* __restrict__ V, const float* __restrict__ lng,
             const float* __restrict__ lnb, float* __restrict__ Out)
{
    __shared__ float sq[1024];
    __shared__ float sv[1024];
    __shared__ float skT[64][16];     // transposed K: [d][g]
    __shared__ float satt[16][17];
    __shared__ float rbuf[2][8];

    const int tid = threadIdx.x;
    const size_t base = (size_t)blockIdx.x * 1024;

    float4 q4 = *(const float4*)&Q[base + tid * 4];
    *(float4*)&sq[tid * 4] = q4;
    float4 v4 = *(const float4*)&V[base + tid * 4];
    *(float4*)&sv[tid * 4] = v4;
    float4 k4 = *(const float4*)&Kp[base + tid * 4];
    {
        int gK = (tid * 4) >> 6;
        int dK = (tid * 4) & 63;
        skT[dK + 0][gK] = k4.x; skT[dK + 1][gK] = k4.y;
        skT[dK + 2][gK] = k4.z; skT[dK + 3][gK] = k4.w;
    }
    __syncthreads();

    // energy: thread (h,g)
    const int h = tid >> 4;
    const int g = tid & 15;
    float e = 0.f;
    #pragma unroll
    for (int d = 0; d < 64; d++) e += sq[h * 64 + d] * skT[d][g];
    satt[h][g] = e * 0.03125f;   // 1/sqrt(1024)
    __syncthreads();

    // softmax per row (16 rows, one thread each)
    if (tid < 16) {
        float mx = -1e30f;
        #pragma unroll
        for (int j = 0; j < 16; j++) mx = fmaxf(mx, satt[tid][j]);
        float s = 0.f;
        #pragma unroll
        for (int j = 0; j < 16; j++) {
            float ex = __expf(satt[tid][j] - mx);
            satt[tid][j] = ex; s += ex;
        }
        float inv = 1.f / s;
        #pragma unroll
        for (int j = 0; j < 16; j++) satt[tid][j] *= inv;
    }
    __syncthreads();

    // head mix: 4 outputs per thread, accumulate LN stats
    float o[4];
    float s1 = 0.f, s2 = 0.f;
    #pragma unroll
    for (int jj = 0; jj < 4; jj++) {
        int p  = tid + 256 * jj;
        int hh = p >> 6;
        int d  = p & 63;
        float acc = 0.f;
        #pragma unroll
        for (int gg = 0; gg < 16; gg++) acc += satt[hh][gg] * sv[gg * 64 + d];
        o[jj] = acc; s1 += acc; s2 += acc * acc;
    }

    // block reduce mean / var
    #pragma unroll
    for (int off = 16; off > 0; off >>= 1) {
        s1 += __shfl_xor_sync(0xffffffffu, s1, off);
        s2 += __shfl_xor_sync(0xffffffffu, s2, off);
    }
    const int wid = tid >> 5, lane = tid & 31;
    if (lane == 0) { rbuf[0][wid] = s1; rbuf[1][wid] = s2; }
    __syncthreads();
    if (tid == 0) {
        float t1 = 0.f, t2 = 0.f;
        #pragma unroll
        for (int w = 0; w < 8; w++) { t1 += rbuf[0][w]; t2 += rbuf[1][w]; }
        float mu  = t1 * (1.f / 1024.f);
        float var = t2 * (1.f / 1024.f) - mu * mu;
        rbuf[0][0] = mu;
        rbuf[1][0] = rsqrtf(var + 1e-5f);
    }
    __syncthreads();
    const float mu = rbuf[0][0], rstd = rbuf[1][0];

    #pragma unroll
    for (int jj = 0; jj < 4; jj++) {
        int p = tid + 256 * jj;
        Out[base + p] = (o[jj] - mu) * rstd * lng[p] + lnb[p];
    }
}

extern "C" void kernel_launch(void* const* d_in, const int* in_sizes, int n_in,
                              void* d_out, int out_size)
{
    const float* query = (const float*)d_in[0];
    const float* key   = (const float*)d_in[1];
    const float* value = (const float*)d_in[2];
    const float* Wq    = (const float*)d_in[3];
    const float* bq    = (const float*)d_in[4];
    const float* Wk    = (const float*)d_in[5];
    const float* bk    = (const float*)d_in[6];
    const float* Wv    = (const float*)d_in[7];
    const float* bv    = (const float*)d_in[8];
    const float* lng   = (const float*)d_in[9];
    const float* lnb   = (const float*)d_in[10];
    const float* Wo    = (const float*)d_in[11];
    const float* bo    = (const float*)d_in[12];
    float* out = (float*)d_out;

    float *pq, *pk, *pv, *px;
    cudaGetSymbolAddress((void**)&pq, g_q);
    cudaGetSymbolAddress((void**)&pk, g_k);
    cudaGetSymbolAddress((void**)&pv, g_v);
    cudaGetSymbolAddress((void**)&px, g_x);

    dim3 gg(DMODEL / 128, M_TOK / 128);   // (8, 128)
    gemm_nt_bias<<<gg, 256>>>(query, Wq, bq, pq, M_TOK, DMODEL, DMODEL);
    gemm_nt_bias<<<gg, 256>>>(key,   Wk, bk, pk, M_TOK, DMODEL, DMODEL);
    gemm_nt_bias<<<gg, 256>>>(value, Wv, bv, pv, M_TOK, DMODEL, DMODEL);
    attn_ln<<<M_TOK, 256>>>(pq, pk, pv, lng, lnb, px);
    gemm_nt_bias<<<gg, 256>>>(px, Wo, bo, out, M_TOK, DMODEL, DMODEL);
}

// round 4
// speedup vs baseline: 2.5136x; 2.5136x over previous
#include <cuda_runtime.h>
#include <cuda_bf16.h>
#include <cstdint>

// ---------------------------------------------------------------------------
// Round 4: baseline-PTX tensor path (harness targets sm_103, no 'a' features).
//   GEMMs via mma.sync.m16n8k16 bf16 (HMMA) with hi/lo split for fp32 accuracy,
//   cp.async 3-stage pipeline, ldmatrix with XOR swizzle.
// ---------------------------------------------------------------------------

#define M_TOK   16384
#define DMODEL  1024
#define NTOK_EL (M_TOK * DMODEL)

__device__ float g_q[NTOK_EL];
__device__ float g_k[NTOK_EL];
__device__ float g_v[NTOK_EL];
__device__ __nv_bfloat16 g_ah[NTOK_EL];
__device__ __nv_bfloat16 g_al[NTOK_EL];
__device__ __nv_bfloat16 g_wh[DMODEL * DMODEL];
__device__ __nv_bfloat16 g_wl[DMODEL * DMODEL];

// ---------------- PTX helpers (all baseline sm_80-era, valid on sm_103) ----
__device__ __forceinline__ uint32_t smem_u32(const void* p) {
    return (uint32_t)__cvta_generic_to_shared(p);
}
__device__ __forceinline__ void cp16(uint32_t dst, const void* src) {
    asm volatile("cp.async.cg.shared.global [%0], [%1], 16;"
                 :: "r"(dst), "l"(src) : "memory");
}
__device__ __forceinline__ void cp_commit() {
    asm volatile("cp.async.commit_group;" ::: "memory");
}
__device__ __forceinline__ void cp_wait1() {
    asm volatile("cp.async.wait_group 1;" ::: "memory");
}
__device__ __forceinline__ void ldsm4(uint32_t* r, uint32_t addr) {
    asm volatile("ldmatrix.sync.aligned.m8n8.x4.shared.b16 {%0,%1,%2,%3}, [%4];"
                 : "=r"(r[0]), "=r"(r[1]), "=r"(r[2]), "=r"(r[3]) : "r"(addr));
}
__device__ __forceinline__ void mma16816(float* c, const uint32_t* a, const uint32_t* b) {
    asm volatile(
        "mma.sync.aligned.m16n8k16.row.col.f32.bf16.bf16.f32 "
        "{%0,%1,%2,%3}, {%4,%5,%6,%7}, {%8,%9}, {%0,%1,%2,%3};"
        : "+f"(c[0]), "+f"(c[1]), "+f"(c[2]), "+f"(c[3])
        : "r"(a[0]), "r"(a[1]), "r"(a[2]), "r"(a[3]), "r"(b[0]), "r"(b[1]));
}

// ---------------- split fp32 -> bf16 hi/lo ----------------
__global__ __launch_bounds__(256)
void split_hl(const float* __restrict__ x, __nv_bfloat16* __restrict__ hi,
              __nv_bfloat16* __restrict__ lo, int n)
{
    int i = (blockIdx.x * 256 + threadIdx.x) * 4;
    if (i >= n) return;
    float4 v = *(const float4*)(x + i);
    __nv_bfloat16 h0 = __float2bfloat16(v.x);
    __nv_bfloat16 h1 = __float2bfloat16(v.y);
    __nv_bfloat16 h2 = __float2bfloat16(v.z);
    __nv_bfloat16 h3 = __float2bfloat16(v.w);
    __nv_bfloat162* H = (__nv_bfloat162*)(hi + i);
    H[0] = __nv_bfloat162(h0, h1);
    H[1] = __nv_bfloat162(h2, h3);
    __nv_bfloat162* L = (__nv_bfloat162*)(lo + i);
    L[0] = __nv_bfloat162(__float2bfloat16(v.x - __bfloat162float(h0)),
                          __float2bfloat16(v.y - __bfloat162float(h1)));
    L[1] = __nv_bfloat162(__float2bfloat16(v.z - __bfloat162float(h2)),
                          __float2bfloat16(v.w - __bfloat162float(h3)));
}

// ---------------- HMMA hi/lo GEMM ----------------
// C[m,n] = sum_k A[m,k]*B[n,k] + bias[n]
// Tile 128x128, BK=32, 3-stage cp.async pipeline.
// SMEM stage: Ah|Al|Bh|Bl, each 128 rows x 32 bf16 (64B rows), XOR-swizzled
// on 16B chunks with (row>>1)&3 -> conflict-free ldmatrix & cp.async.
#define BK          32
#define MAT_BYTES   8192          // 128 * 64B
#define STAGE_BYTES 32768         // 4 matrices
#define STAGES      3
#define GEMM_SMEM   (STAGES * STAGE_BYTES)

struct SrcPtrs { const __nv_bfloat16* p[4]; };   // Ah, Al, Bh, Bl

__device__ __forceinline__ void load_stage(const SrcPtrs& S, int kb, uint32_t sdst,
                                           int tid, int m0, int n0, int K)
{
    #pragma unroll
    for (int i = 0; i < 8; i++) {
        const int id  = i * 256 + tid;
        const int mat = id >> 9;
        const int idx = id & 511;
        const int row = idx >> 2;
        const int ch  = idx & 3;
        const int grow = ((mat < 2) ? m0 : n0) + row;
        const void* g = S.p[mat] + (size_t)grow * K + kb * BK + ch * 8;
        const uint32_t d = sdst + mat * MAT_BYTES + row * 64
                         + (((uint32_t)(ch ^ ((row >> 1) & 3))) << 4);
        cp16(d, g);
    }
}

__global__ __launch_bounds__(256, 1)
void gemm_mma(const __nv_bfloat16* __restrict__ Ah, const __nv_bfloat16* __restrict__ Al,
              const __nv_bfloat16* __restrict__ Bh, const __nv_bfloat16* __restrict__ Bl,
              const float* __restrict__ bias, float* __restrict__ C,
              int K, int Ntot)
{
    extern __shared__ char smem[];
    const uint32_t sbase = smem_u32(smem);
    const int tid  = threadIdx.x;
    const int lane = tid & 31;
    const int wid  = tid >> 5;
    const int wm   = wid >> 1;       // 0..3 -> m offset wm*32
    const int wn   = wid & 1;        // 0..1 -> n offset wn*64
    const int m0 = blockIdx.y * 128;
    const int n0 = blockIdx.x * 128;

    SrcPtrs S; S.p[0] = Ah; S.p[1] = Al; S.p[2] = Bh; S.p[3] = Bl;

    // per-lane ldmatrix addressing invariants
    const int g = lane >> 3, j = lane & 7;
    const int cA = g >> 1;                              // A chunk offset
    const int rowA_base = wm * 32 + ((g & 1) ? 8 : 0) + j;
    const int cB = g & 1;                               // B chunk offset
    const int rowB_base = wn * 64 + ((g >> 1) ? 8 : 0) + j;

    float acc[2][8][4];
    #pragma unroll
    for (int a = 0; a < 2; a++)
        #pragma unroll
        for (int b = 0; b < 8; b++)
            #pragma unroll
            for (int c = 0; c < 4; c++) acc[a][b][c] = 0.f;

    const int nkb = K / BK;       // 32
    load_stage(S, 0, sbase,               tid, m0, n0, K); cp_commit();
    load_stage(S, 1, sbase + STAGE_BYTES, tid, m0, n0, K); cp_commit();

    for (int kb = 0; kb < nkb; kb++) {
        const int s = kb % STAGES;
        cp_wait1();
        __syncthreads();
        const uint32_t st = sbase + s * STAGE_BYTES;

        #pragma unroll
        for (int k16 = 0; k16 < 2; k16++) {
            const int c0 = k16 * 2;
            uint32_t ah[2][4], al[2][4];
            uint32_t bh[16], bl[16];

            #pragma unroll
            for (int mf = 0; mf < 2; mf++) {
                const int row = rowA_base + mf * 16;
                const uint32_t ad = st + row * 64
                    + (((uint32_t)((c0 + cA) ^ ((row >> 1) & 3))) << 4);
                ldsm4(ah[mf], ad);
                ldsm4(al[mf], ad + MAT_BYTES);
            }
            #pragma unroll
            for (int p = 0; p < 4; p++) {
                const int row = rowB_base + p * 16;
                const uint32_t bd = st + 2 * MAT_BYTES + row * 64
                    + (((uint32_t)((c0 + cB) ^ ((row >> 1) & 3))) << 4);
                ldsm4(&bh[p * 4], bd);
                ldsm4(&bl[p * 4], bd + MAT_BYTES);
            }

            #pragma unroll
            for (int mf = 0; mf < 2; mf++)
                #pragma unroll
                for (int nf = 0; nf < 8; nf++) {
                    mma16816(acc[mf][nf], ah[mf], &bh[nf * 2]);
                    mma16816(acc[mf][nf], ah[mf], &bl[nf * 2]);
                    mma16816(acc[mf][nf], al[mf], &bh[nf * 2]);
                }
        }
        __syncthreads();
        if (kb + 2 < nkb)
            load_stage(S, kb + 2, sbase + ((kb + 2) % STAGES) * STAGE_BYTES,
                       tid, m0, n0, K);
        cp_commit();
    }

    // epilogue
    const int rl = lane >> 2;
    const int cl = (lane & 3) * 2;
    #pragma unroll
    for (int mf = 0; mf < 2; mf++) {
        const int grow = m0 + wm * 32 + mf * 16 + rl;
        #pragma unroll
        for (int nf = 0; nf < 8; nf++) {
            const int gcol = n0 + wn * 64 + nf * 8 + cl;
            const float2 b2 = *(const float2*)&bias[gcol];
            float2 o0 = make_float2(acc[mf][nf][0] + b2.x, acc[mf][nf][1] + b2.y);
            float2 o1 = make_float2(acc[mf][nf][2] + b2.x, acc[mf][nf][3] + b2.y);
            *(float2*)&C[(size_t)grow * Ntot + gcol]       = o0;
            *(float2*)&C[(size_t)(grow + 8) * Ntot + gcol] = o1;
        }
    }
}

// ---------------- per-token head-mix attention + LayerNorm ----------------
__global__ __launch_bounds__(256)
void attn_ln(const float* __restrict__ Q, const float* __restrict__ Kp,
             const float* __restrict__ V, const float* __restrict__ lng,
             const float* __restrict__ lnb,
             __nv_bfloat16* __restrict__ Xh, __nv_bfloat16* __restrict__ Xl)
{
    __shared__ float sq[1024];
    __shared__ float sv[1024];
    __shared__ float skT[64][16];
    __shared__ float satt[16][17];
    __shared__ float rbuf[2][8];

    const int tid = threadIdx.x;
    const size_t base = (size_t)blockIdx.x * 1024;

    float4 q4 = *(const float4*)&Q[base + tid * 4];
    *(float4*)&sq[tid * 4] = q4;
    float4 v4 = *(const float4*)&V[base + tid * 4];
    *(float4*)&sv[tid * 4] = v4;
    float4 k4 = *(const float4*)&Kp[base + tid * 4];
    {
        int gK = (tid * 4) >> 6;
        int dK = (tid * 4) & 63;
        skT[dK + 0][gK] = k4.x; skT[dK + 1][gK] = k4.y;
        skT[dK + 2][gK] = k4.z; skT[dK + 3][gK] = k4.w;
    }
    __syncthreads();

    const int h = tid >> 4;
    const int g = tid & 15;
    float e = 0.f;
    #pragma unroll
    for (int d = 0; d < 64; d++) e += sq[h * 64 + d] * skT[d][g];
    satt[h][g] = e * 0.03125f;
    __syncthreads();

    if (tid < 16) {
        float mx = -1e30f;
        #pragma unroll
        for (int j = 0; j < 16; j++) mx = fmaxf(mx, satt[tid][j]);
        float s = 0.f;
        #pragma unroll
        for (int j = 0; j < 16; j++) {
            float ex = __expf(satt[tid][j] - mx);
            satt[tid][j] = ex; s += ex;
        }
        float inv = 1.f / s;
        #pragma unroll
        for (int j = 0; j < 16; j++) satt[tid][j] *= inv;
    }
    __syncthreads();

    float o[4];
    float s1 = 0.f, s2 = 0.f;
    #pragma unroll
    for (int jj = 0; jj < 4; jj++) {
        int p  = tid + 256 * jj;
        int hh = p >> 6;
        int d  = p & 63;
        float acc = 0.f;
        #pragma unroll
        for (int gg = 0; gg < 16; gg++) acc += satt[hh][gg] * sv[gg * 64 + d];
        o[jj] = acc; s1 += acc; s2 += acc * acc;
    }

    #pragma unroll
    for (int off = 16; off > 0; off >>= 1) {
        s1 += __shfl_xor_sync(0xffffffffu, s1, off);
        s2 += __shfl_xor_sync(0xffffffffu, s2, off);
    }
    const int wid = tid >> 5, lane = tid & 31;
    if (lane == 0) { rbuf[0][wid] = s1; rbuf[1][wid] = s2; }
    __syncthreads();
    if (tid == 0) {
        float t1 = 0.f, t2 = 0.f;
        #pragma unroll
        for (int w = 0; w < 8; w++) { t1 += rbuf[0][w]; t2 += rbuf[1][w]; }
        float mu  = t1 * (1.f / 1024.f);
        float var = t2 * (1.f / 1024.f) - mu * mu;
        rbuf[0][0] = mu;
        rbuf[1][0] = rsqrtf(var + 1e-5f);
    }
    __syncthreads();
    const float mu = rbuf[0][0], rstd = rbuf[1][0];

    #pragma unroll
    for (int jj = 0; jj < 4; jj++) {
        int p = tid + 256 * jj;
        float val = (o[jj] - mu) * rstd * lng[p] + lnb[p];
        __nv_bfloat16 hi = __float2bfloat16(val);
        Xh[base + p] = hi;
        Xl[base + p] = __float2bfloat16(val - __bfloat162float(hi));
    }
}

// ---------------- launch ----------------
extern "C" void kernel_launch(void* const* d_in, const int* in_sizes, int n_in,
                              void* d_out, int out_size)
{
    const float* query = (const float*)d_in[0];
    const float* key   = (const float*)d_in[1];
    const float* value = (const float*)d_in[2];
    const float* Wq    = (const float*)d_in[3];
    const float* bq    = (const float*)d_in[4];
    const float* Wk    = (const float*)d_in[5];
    const float* bk    = (const float*)d_in[6];
    const float* Wv    = (const float*)d_in[7];
    const float* bv    = (const float*)d_in[8];
    const float* lng   = (const float*)d_in[9];
    const float* lnb   = (const float*)d_in[10];
    const float* Wo    = (const float*)d_in[11];
    const float* bo    = (const float*)d_in[12];
    float* out = (float*)d_out;

    float *pq, *pk, *pv;
    __nv_bfloat16 *pah, *pal, *pwh, *pwl;
    cudaGetSymbolAddress((void**)&pq,  g_q);
    cudaGetSymbolAddress((void**)&pk,  g_k);
    cudaGetSymbolAddress((void**)&pv,  g_v);
    cudaGetSymbolAddress((void**)&pah, g_ah);
    cudaGetSymbolAddress((void**)&pal, g_al);
    cudaGetSymbolAddress((void**)&pwh, g_wh);
    cudaGetSymbolAddress((void**)&pwl, g_wl);

    cudaFuncSetAttribute(gemm_mma, cudaFuncAttributeMaxDynamicSharedMemorySize, GEMM_SMEM);

    const int nAct = NTOK_EL;            // 16M
    const int nW   = DMODEL * DMODEL;    // 1M
    dim3 gg(DMODEL / 128, M_TOK / 128);  // (8, 128)

    // Q
    split_hl<<<nAct / 1024, 256>>>(query, pah, pal, nAct);
    split_hl<<<nW   / 1024, 256>>>(Wq,    pwh, pwl, nW);
    gemm_mma<<<gg, 256, GEMM_SMEM>>>(pah, pal, pwh, pwl, bq, pq, DMODEL, DMODEL);
    // K
    split_hl<<<nAct / 1024, 256>>>(key, pah, pal, nAct);
    split_hl<<<nW   / 1024, 256>>>(Wk,  pwh, pwl, nW);
    gemm_mma<<<gg, 256, GEMM_SMEM>>>(pah, pal, pwh, pwl, bk, pk, DMODEL, DMODEL);
    // V
    split_hl<<<nAct / 1024, 256>>>(value, pah, pal, nAct);
    split_hl<<<nW   / 1024, 256>>>(Wv,    pwh, pwl, nW);
    gemm_mma<<<gg, 256, GEMM_SMEM>>>(pah, pal, pwh, pwl, bv, pv, DMODEL, DMODEL);
    // attention + LN -> hi/lo directly
    attn_ln<<<M_TOK, 256>>>(pq, pk, pv, lng, lnb, pah, pal);
    // output projection
    split_hl<<<nW / 1024, 256>>>(Wo, pwh, pwl, nW);
    gemm_mma<<<gg, 256, GEMM_SMEM>>>(pah, pal, pwh, pwl, bo, out, DMODEL, DMODEL);
}

// round 5
// speedup vs baseline: 3.2764x; 1.3035x over previous
#include <cuda_runtime.h>
#include <cuda_fp16.h>
#include <cstdint>

// ---------------------------------------------------------------------------
// Round 5: fp16 2-term GEMMs.
//   activations: single fp16 (rel err ~2.8e-4 rms)
//   weights:     fp16 hi/lo split (exact to ~2^-18)
//   D = A*Wh + A*Wl  -> 2 HMMA terms (was 3 bf16 terms)
// ---------------------------------------------------------------------------

#define M_TOK   16384
#define DMODEL  1024
#define NTOK_EL (M_TOK * DMODEL)

__device__ float  g_q[NTOK_EL];
__device__ float  g_k[NTOK_EL];
__device__ float  g_v[NTOK_EL];
__device__ __half g_a16[NTOK_EL];
__device__ __half g_wh[DMODEL * DMODEL];
__device__ __half g_wl[DMODEL * DMODEL];

// ---------------- PTX helpers (baseline sm_80-era) ----------------
__device__ __forceinline__ uint32_t smem_u32(const void* p) {
    return (uint32_t)__cvta_generic_to_shared(p);
}
__device__ __forceinline__ void cp16(uint32_t dst, const void* src) {
    asm volatile("cp.async.cg.shared.global [%0], [%1], 16;"
                 :: "r"(dst), "l"(src) : "memory");
}
__device__ __forceinline__ void cp_commit() {
    asm volatile("cp.async.commit_group;" ::: "memory");
}
__device__ __forceinline__ void cp_wait1() {
    asm volatile("cp.async.wait_group 1;" ::: "memory");
}
__device__ __forceinline__ void ldsm4(uint32_t* r, uint32_t addr) {
    asm volatile("ldmatrix.sync.aligned.m8n8.x4.shared.b16 {%0,%1,%2,%3}, [%4];"
                 : "=r"(r[0]), "=r"(r[1]), "=r"(r[2]), "=r"(r[3]) : "r"(addr));
}
__device__ __forceinline__ void mma16816(float* c, const uint32_t* a, const uint32_t* b) {
    asm volatile(
        "mma.sync.aligned.m16n8k16.row.col.f32.f16.f16.f32 "
        "{%0,%1,%2,%3}, {%4,%5,%6,%7}, {%8,%9}, {%0,%1,%2,%3};"
        : "+f"(c[0]), "+f"(c[1]), "+f"(c[2]), "+f"(c[3])
        : "r"(a[0]), "r"(a[1]), "r"(a[2]), "r"(a[3]), "r"(b[0]), "r"(b[1]));
}

// ---------------- converts ----------------
// fp32 -> fp16 (activations), 8 elems/thread
__global__ __launch_bounds__(256)
void to_f16(const float* __restrict__ x, __half* __restrict__ y, int n)
{
    int i = (blockIdx.x * 256 + threadIdx.x) * 8;
    if (i >= n) return;
    float4 v0 = *(const float4*)(x + i);
    float4 v1 = *(const float4*)(x + i + 4);
    __half2 h[4];
    h[0] = __floats2half2_rn(v0.x, v0.y);
    h[1] = __floats2half2_rn(v0.z, v0.w);
    h[2] = __floats2half2_rn(v1.x, v1.y);
    h[3] = __floats2half2_rn(v1.z, v1.w);
    *(uint4*)(y + i) = *(uint4*)h;
}

// fp32 -> fp16 hi/lo (weights)
__global__ __launch_bounds__(256)
void split_w(const float* __restrict__ x, __half* __restrict__ hi,
             __half* __restrict__ lo, int n)
{
    int i = (blockIdx.x * 256 + threadIdx.x) * 4;
    if (i >= n) return;
    float4 v = *(const float4*)(x + i);
    __half h0 = __float2half_rn(v.x);
    __half h1 = __float2half_rn(v.y);
    __half h2 = __float2half_rn(v.z);
    __half h3 = __float2half_rn(v.w);
    __half2* H = (__half2*)(hi + i);
    H[0] = __half2(h0, h1);
    H[1] = __half2(h2, h3);
    __half2* L = (__half2*)(lo + i);
    L[0] = __half2(__float2half_rn(v.x - __half2float(h0)),
                   __float2half_rn(v.y - __half2float(h1)));
    L[1] = __half2(__float2half_rn(v.z - __half2float(h2)),
                   __float2half_rn(v.w - __half2float(h3)));
}

// ---------------- HMMA 2-term GEMM ----------------
// C[m,n] = sum_k A[m,k]*(Wh[n,k]+Wl[n,k]) + bias[n]
// Tile 128x128, BK=32, 3-stage cp.async pipeline.
// SMEM stage: A | Wh | Wl, each 128 rows x 32 fp16 (64B rows), XOR-swizzled.
#define BK          32
#define MAT_BYTES   8192          // 128 * 64B
#define STAGE_BYTES 24576         // 3 matrices
#define STAGES      3
#define GEMM_SMEM   (STAGES * STAGE_BYTES)

struct SrcPtrs { const __half* p[3]; };   // A, Wh, Wl

__device__ __forceinline__ void load_stage(const SrcPtrs& S, int kb, uint32_t sdst,
                                           int tid, int m0, int n0, int K)
{
    #pragma unroll
    for (int i = 0; i < 6; i++) {
        const int id  = i * 256 + tid;
        const int mat = id >> 9;                // 0:A 1:Wh 2:Wl
        const int idx = id & 511;
        const int row = idx >> 2;
        const int ch  = idx & 3;
        const int grow = ((mat == 0) ? m0 : n0) + row;
        const void* g = S.p[mat] + (size_t)grow * K + kb * BK + ch * 8;
        const uint32_t d = sdst + mat * MAT_BYTES + row * 64
                         + (((uint32_t)(ch ^ ((row >> 1) & 3))) << 4);
        cp16(d, g);
    }
}

__global__ __launch_bounds__(256, 1)
void gemm_mma(const __half* __restrict__ A, const __half* __restrict__ Wh,
              const __half* __restrict__ Wl,
              const float* __restrict__ bias, float* __restrict__ C,
              int K, int Ntot)
{
    extern __shared__ char smem[];
    const uint32_t sbase = smem_u32(smem);
    const int tid  = threadIdx.x;
    const int lane = tid & 31;
    const int wid  = tid >> 5;
    const int wm   = wid >> 1;       // 0..3 -> m offset wm*32
    const int wn   = wid & 1;        // 0..1 -> n offset wn*64
    const int m0 = blockIdx.y * 128;
    const int n0 = blockIdx.x * 128;

    SrcPtrs S; S.p[0] = A; S.p[1] = Wh; S.p[2] = Wl;

    const int g = lane >> 3, j = lane & 7;
    const int cA = g >> 1;
    const int rowA_base = wm * 32 + ((g & 1) ? 8 : 0) + j;
    const int cB = g & 1;
    const int rowB_base = wn * 64 + ((g >> 1) ? 8 : 0) + j;

    float acc[2][8][4];
    #pragma unroll
    for (int a = 0; a < 2; a++)
        #pragma unroll
        for (int b = 0; b < 8; b++)
            #pragma unroll
            for (int c = 0; c < 4; c++) acc[a][b][c] = 0.f;

    const int nkb = K / BK;       // 32
    load_stage(S, 0, sbase,               tid, m0, n0, K); cp_commit();
    load_stage(S, 1, sbase + STAGE_BYTES, tid, m0, n0, K); cp_commit();

    for (int kb = 0; kb < nkb; kb++) {
        const int s = kb % STAGES;
        cp_wait1();
        __syncthreads();
        const uint32_t st = sbase + s * STAGE_BYTES;

        #pragma unroll
        for (int k16 = 0; k16 < 2; k16++) {
            const int c0 = k16 * 2;
            uint32_t ar[2][4];
            uint32_t bh[16], bl[16];

            #pragma unroll
            for (int mf = 0; mf < 2; mf++) {
                const int row = rowA_base + mf * 16;
                const uint32_t ad = st + row * 64
                    + (((uint32_t)((c0 + cA) ^ ((row >> 1) & 3))) << 4);
                ldsm4(ar[mf], ad);
            }
            #pragma unroll
            for (int p = 0; p < 4; p++) {
                const int row = rowB_base + p * 16;
                const uint32_t bd = st + MAT_BYTES + row * 64
                    + (((uint32_t)((c0 + cB) ^ ((row >> 1) & 3))) << 4);
                ldsm4(&bh[p * 4], bd);
                ldsm4(&bl[p * 4], bd + MAT_BYTES);
            }

            #pragma unroll
            for (int mf = 0; mf < 2; mf++)
                #pragma unroll
                for (int nf = 0; nf < 8; nf++) {
                    mma16816(acc[mf][nf], ar[mf], &bh[nf * 2]);
                    mma16816(acc[mf][nf], ar[mf], &bl[nf * 2]);
                }
        }
        __syncthreads();
        if (kb + 2 < nkb)
            load_stage(S, kb + 2, sbase + ((kb + 2) % STAGES) * STAGE_BYTES,
                       tid, m0, n0, K);
        cp_commit();
    }

    // epilogue
    const int rl = lane >> 2;
    const int cl = (lane & 3) * 2;
    #pragma unroll
    for (int mf = 0; mf < 2; mf++) {
        const int grow = m0 + wm * 32 + mf * 16 + rl;
        #pragma unroll
        for (int nf = 0; nf < 8; nf++) {
            const int gcol = n0 + wn * 64 + nf * 8 + cl;
            const float2 b2 = *(const float2*)&bias[gcol];
            float2 o0 = make_float2(acc[mf][nf][0] + b2.x, acc[mf][nf][1] + b2.y);
            float2 o1 = make_float2(acc[mf][nf][2] + b2.x, acc[mf][nf][3] + b2.y);
            *(float2*)&C[(size_t)grow * Ntot + gcol]       = o0;
            *(float2*)&C[(size_t)(grow + 8) * Ntot + gcol] = o1;
        }
    }
}

// ---------------- per-token head-mix attention + LayerNorm ----------------
// Emits fp16 X for the final GEMM.
__global__ __launch_bounds__(256)
void attn_ln(const float* __restrict__ Q, const float* __restrict__ Kp,
             const float* __restrict__ V, const float* __restrict__ lng,
             const float* __restrict__ lnb, __half* __restrict__ X)
{
    __shared__ float sq[1024];
    __shared__ float sv[1024];
    __shared__ float skT[64][16];
    __shared__ float satt[16][17];
    __shared__ float rbuf[2][8];

    const int tid = threadIdx.x;
    const size_t base = (size_t)blockIdx.x * 1024;

    float4 q4 = *(const float4*)&Q[base + tid * 4];
    *(float4*)&sq[tid * 4] = q4;
    float4 v4 = *(const float4*)&V[base + tid * 4];
    *(float4*)&sv[tid * 4] = v4;
    float4 k4 = *(const float4*)&Kp[base + tid * 4];
    {
        int gK = (tid * 4) >> 6;
        int dK = (tid * 4) & 63;
        skT[dK + 0][gK] = k4.x; skT[dK + 1][gK] = k4.y;
        skT[dK + 2][gK] = k4.z; skT[dK + 3][gK] = k4.w;
    }
    __syncthreads();

    const int h = tid >> 4;
    const int g = tid & 15;
    float e = 0.f;
    #pragma unroll
    for (int d = 0; d < 64; d++) e += sq[h * 64 + d] * skT[d][g];
    satt[h][g] = e * 0.03125f;
    __syncthreads();

    if (tid < 16) {
        float mx = -1e30f;
        #pragma unroll
        for (int j = 0; j < 16; j++) mx = fmaxf(mx, satt[tid][j]);
        float s = 0.f;
        #pragma unroll
        for (int j = 0; j < 16; j++) {
            float ex = __expf(satt[tid][j] - mx);
            satt[tid][j] = ex; s += ex;
        }
        float inv = 1.f / s;
        #pragma unroll
        for (int j = 0; j < 16; j++) satt[tid][j] *= inv;
    }
    __syncthreads();

    float o[4];
    float s1 = 0.f, s2 = 0.f;
    #pragma unroll
    for (int jj = 0; jj < 4; jj++) {
        int p  = tid + 256 * jj;
        int hh = p >> 6;
        int d  = p & 63;
        float acc = 0.f;
        #pragma unroll
        for (int gg = 0; gg < 16; gg++) acc += satt[hh][gg] * sv[gg * 64 + d];
        o[jj] = acc; s1 += acc; s2 += acc * acc;
    }

    #pragma unroll
    for (int off = 16; off > 0; off >>= 1) {
        s1 += __shfl_xor_sync(0xffffffffu, s1, off);
        s2 += __shfl_xor_sync(0xffffffffu, s2, off);
    }
    const int wid = tid >> 5, lane = tid & 31;
    if (lane == 0) { rbuf[0][wid] = s1; rbuf[1][wid] = s2; }
    __syncthreads();
    if (tid == 0) {
        float t1 = 0.f, t2 = 0.f;
        #pragma unroll
        for (int w = 0; w < 8; w++) { t1 += rbuf[0][w]; t2 += rbuf[1][w]; }
        float mu  = t1 * (1.f / 1024.f);
        float var = t2 * (1.f / 1024.f) - mu * mu;
        rbuf[0][0] = mu;
        rbuf[1][0] = rsqrtf(var + 1e-5f);
    }
    __syncthreads();
    const float mu = rbuf[0][0], rstd = rbuf[1][0];

    #pragma unroll
    for (int jj = 0; jj < 4; jj++) {
        int p = tid + 256 * jj;
        float val = (o[jj] - mu) * rstd * lng[p] + lnb[p];
        X[base + p] = __float2half_rn(val);
    }
}

// ---------------- launch ----------------
extern "C" void kernel_launch(void* const* d_in, const int* in_sizes, int n_in,
                              void* d_out, int out_size)
{
    const float* query = (const float*)d_in[0];
    const float* key   = (const float*)d_in[1];
    const float* value = (const float*)d_in[2];
    const float* Wq    = (const float*)d_in[3];
    const float* bq    = (const float*)d_in[4];
    const float* Wk    = (const float*)d_in[5];
    const float* bk    = (const float*)d_in[6];
    const float* Wv    = (const float*)d_in[7];
    const float* bv    = (const float*)d_in[8];
    const float* lng   = (const float*)d_in[9];
    const float* lnb   = (const float*)d_in[10];
    const float* Wo    = (const float*)d_in[11];
    const float* bo    = (const float*)d_in[12];
    float* out = (float*)d_out;

    float *pq, *pk, *pv;
    __half *pa, *pwh, *pwl;
    cudaGetSymbolAddress((void**)&pq,  g_q);
    cudaGetSymbolAddress((void**)&pk,  g_k);
    cudaGetSymbolAddress((void**)&pv,  g_v);
    cudaGetSymbolAddress((void**)&pa,  g_a16);
    cudaGetSymbolAddress((void**)&pwh, g_wh);
    cudaGetSymbolAddress((void**)&pwl, g_wl);

    cudaFuncSetAttribute(gemm_mma, cudaFuncAttributeMaxDynamicSharedMemorySize, GEMM_SMEM);

    const int nAct = NTOK_EL;            // 16M
    const int nW   = DMODEL * DMODEL;    // 1M
    dim3 gg(DMODEL / 128, M_TOK / 128);  // (8, 128)

    // Q
    to_f16<<<nAct / 2048, 256>>>(query, pa, nAct);
    split_w<<<nW / 1024, 256>>>(Wq, pwh, pwl, nW);
    gemm_mma<<<gg, 256, GEMM_SMEM>>>(pa, pwh, pwl, bq, pq, DMODEL, DMODEL);
    // K
    to_f16<<<nAct / 2048, 256>>>(key, pa, nAct);
    split_w<<<nW / 1024, 256>>>(Wk, pwh, pwl, nW);
    gemm_mma<<<gg, 256, GEMM_SMEM>>>(pa, pwh, pwl, bk, pk, DMODEL, DMODEL);
    // V
    to_f16<<<nAct / 2048, 256>>>(value, pa, nAct);
    split_w<<<nW / 1024, 256>>>(Wv, pwh, pwl, nW);
    gemm_mma<<<gg, 256, GEMM_SMEM>>>(pa, pwh, pwl, bv, pv, DMODEL, DMODEL);
    // attention + LN -> fp16 X
    attn_ln<<<M_TOK, 256>>>(pq, pk, pv, lng, lnb, pa);
    // output projection
    split_w<<<nW / 1024, 256>>>(Wo, pwh, pwl, nW);
    gemm_mma<<<gg, 256, GEMM_SMEM>>>(pa, pwh, pwl, bo, out, DMODEL, DMODEL);
}

// round 6
// speedup vs baseline: 4.4309x; 1.3524x over previous
#include <cuda_runtime.h>
#include <cuda_fp16.h>
#include <cstdint>

// ---------------------------------------------------------------------------
// Round 6: 1-term fp16 GEMMs (weights single-rounded fp16) + float4 attn_ln.
//   D = A16 * W16 + bias   (one HMMA term; rel_err budget ~5e-4 vs 1e-3 gate)
// ---------------------------------------------------------------------------

#define M_TOK   16384
#define DMODEL  1024
#define NTOK_EL (M_TOK * DMODEL)

__device__ float  g_q[NTOK_EL];
__device__ float  g_k[NTOK_EL];
__device__ float  g_v[NTOK_EL];
__device__ __half g_a16[NTOK_EL];
__device__ __half g_w16[DMODEL * DMODEL];

// ---------------- PTX helpers (baseline sm_80-era) ----------------
__device__ __forceinline__ uint32_t smem_u32(const void* p) {
    return (uint32_t)__cvta_generic_to_shared(p);
}
__device__ __forceinline__ void cp16(uint32_t dst, const void* src) {
    asm volatile("cp.async.cg.shared.global [%0], [%1], 16;"
                 :: "r"(dst), "l"(src) : "memory");
}
__device__ __forceinline__ void cp_commit() {
    asm volatile("cp.async.commit_group;" ::: "memory");
}
__device__ __forceinline__ void cp_wait1() {
    asm volatile("cp.async.wait_group 1;" ::: "memory");
}
__device__ __forceinline__ void ldsm4(uint32_t* r, uint32_t addr) {
    asm volatile("ldmatrix.sync.aligned.m8n8.x4.shared.b16 {%0,%1,%2,%3}, [%4];"
                 : "=r"(r[0]), "=r"(r[1]), "=r"(r[2]), "=r"(r[3]) : "r"(addr));
}
__device__ __forceinline__ void mma16816(float* c, const uint32_t* a, const uint32_t* b) {
    asm volatile(
        "mma.sync.aligned.m16n8k16.row.col.f32.f16.f16.f32 "
        "{%0,%1,%2,%3}, {%4,%5,%6,%7}, {%8,%9}, {%0,%1,%2,%3};"
        : "+f"(c[0]), "+f"(c[1]), "+f"(c[2]), "+f"(c[3])
        : "r"(a[0]), "r"(a[1]), "r"(a[2]), "r"(a[3]), "r"(b[0]), "r"(b[1]));
}

// ---------------- convert fp32 -> fp16, 8 elems/thread ----------------
__global__ __launch_bounds__(256)
void to_f16(const float* __restrict__ x, __half* __restrict__ y, int n)
{
    int i = (blockIdx.x * 256 + threadIdx.x) * 8;
    if (i >= n) return;
    float4 v0 = *(const float4*)(x + i);
    float4 v1 = *(const float4*)(x + i + 4);
    __half2 h[4];
    h[0] = __floats2half2_rn(v0.x, v0.y);
    h[1] = __floats2half2_rn(v0.z, v0.w);
    h[2] = __floats2half2_rn(v1.x, v1.y);
    h[3] = __floats2half2_rn(v1.z, v1.w);
    *(uint4*)(y + i) = *(uint4*)h;
}

// ---------------- HMMA 1-term GEMM ----------------
// C[m,n] = sum_k A[m,k]*W[n,k] + bias[n]
// Tile 128x128, BK=32, 3-stage cp.async pipeline.
// SMEM stage: A | W, each 128 rows x 32 fp16 (64B rows), XOR-swizzled.
#define BK          32
#define MAT_BYTES   8192          // 128 * 64B
#define STAGE_BYTES 16384         // 2 matrices
#define STAGES      3
#define GEMM_SMEM   (STAGES * STAGE_BYTES)

__device__ __forceinline__ void load_stage(const __half* A, const __half* W,
                                           int kb, uint32_t sdst,
                                           int tid, int m0, int n0, int K)
{
    #pragma unroll
    for (int i = 0; i < 4; i++) {
        const int id  = i * 256 + tid;
        const int mat = id >> 9;                // 0:A 1:W
        const int idx = id & 511;
        const int row = idx >> 2;
        const int ch  = idx & 3;
        const int grow = ((mat == 0) ? m0 : n0) + row;
        const __half* src = (mat == 0) ? A : W;
        const void* g = src + (size_t)grow * K + kb * BK + ch * 8;
        const uint32_t d = sdst + mat * MAT_BYTES + row * 64
                         + (((uint32_t)(ch ^ ((row >> 1) & 3))) << 4);
        cp16(d, g);
    }
}

__global__ __launch_bounds__(256, 1)
void gemm_mma(const __half* __restrict__ A, const __half* __restrict__ W,
              const float* __restrict__ bias, float* __restrict__ C,
              int K, int Ntot)
{
    extern __shared__ char smem[];
    const uint32_t sbase = smem_u32(smem);
    const int tid  = threadIdx.x;
    const int lane = tid & 31;
    const int wid  = tid >> 5;
    const int wm   = wid >> 1;       // 0..3 -> m offset wm*32
    const int wn   = wid & 1;        // 0..1 -> n offset wn*64
    const int m0 = blockIdx.y * 128;
    const int n0 = blockIdx.x * 128;

    const int g = lane >> 3, j = lane & 7;
    const int cA = g >> 1;
    const int rowA_base = wm * 32 + ((g & 1) ? 8 : 0) + j;
    const int cB = g & 1;
    const int rowB_base = wn * 64 + ((g >> 1) ? 8 : 0) + j;

    float acc[2][8][4];
    #pragma unroll
    for (int a = 0; a < 2; a++)
        #pragma unroll
        for (int b = 0; b < 8; b++)
            #pragma unroll
            for (int c = 0; c < 4; c++) acc[a][b][c] = 0.f;

    const int nkb = K / BK;       // 32
    load_stage(A, W, 0, sbase,               tid, m0, n0, K); cp_commit();
    load_stage(A, W, 1, sbase + STAGE_BYTES, tid, m0, n0, K); cp_commit();

    for (int kb = 0; kb < nkb; kb++) {
        const int s = kb % STAGES;
        cp_wait1();
        __syncthreads();
        const uint32_t st = sbase + s * STAGE_BYTES;

        #pragma unroll
        for (int k16 = 0; k16 < 2; k16++) {
            const int c0 = k16 * 2;
            uint32_t ar[2][4];
            uint32_t bw[16];

            #pragma unroll
            for (int mf = 0; mf < 2; mf++) {
                const int row = rowA_base + mf * 16;
                const uint32_t ad = st + row * 64
                    + (((uint32_t)((c0 + cA) ^ ((row >> 1) & 3))) << 4);
                ldsm4(ar[mf], ad);
            }
            #pragma unroll
            for (int p = 0; p < 4; p++) {
                const int row = rowB_base + p * 16;
                const uint32_t bd = st + MAT_BYTES + row * 64
                    + (((uint32_t)((c0 + cB) ^ ((row >> 1) & 3))) << 4);
                ldsm4(&bw[p * 4], bd);
            }

            #pragma unroll
            for (int mf = 0; mf < 2; mf++)
                #pragma unroll
                for (int nf = 0; nf < 8; nf++)
                    mma16816(acc[mf][nf], ar[mf], &bw[nf * 2]);
        }
        __syncthreads();
        if (kb + 2 < nkb)
            load_stage(A, W, kb + 2, sbase + ((kb + 2) % STAGES) * STAGE_BYTES,
                       tid, m0, n0, K);
        cp_commit();
    }

    // epilogue
    const int rl = lane >> 2;
    const int cl = (lane & 3) * 2;
    #pragma unroll
    for (int mf = 0; mf < 2; mf++) {
        const int grow = m0 + wm * 32 + mf * 16 + rl;
        #pragma unroll
        for (int nf = 0; nf < 8; nf++) {
            const int gcol = n0 + wn * 64 + nf * 8 + cl;
            const float2 b2 = *(const float2*)&bias[gcol];
            float2 o0 = make_float2(acc[mf][nf][0] + b2.x, acc[mf][nf][1] + b2.y);
            float2 o1 = make_float2(acc[mf][nf][2] + b2.x, acc[mf][nf][3] + b2.y);
            *(float2*)&C[(size_t)grow * Ntot + gcol]       = o0;
            *(float2*)&C[(size_t)(grow + 8) * Ntot + gcol] = o1;
        }
    }
}

// ---------------- per-token head-mix attention + LayerNorm (float4) -------
// energy[h,g] = q_h . k_g ; softmax over g ; out[h,:] = sum_g attn * v_g ; LN.
__global__ __launch_bounds__(256)
void attn_ln(const float* __restrict__ Q, const float* __restrict__ Kp,
             const float* __restrict__ V, const float* __restrict__ lng,
             const float* __restrict__ lnb, __half* __restrict__ X)
{
    __shared__ float4 sq4[256];        // [h*16 + d4]
    __shared__ float4 sv4[256];        // [g*16 + d4]
    __shared__ float4 sk4[16 * 17];    // [g*17 + d4] (padded rows)
    __shared__ float  satt[16][17];
    __shared__ float  rbuf[2][8];

    const int tid = threadIdx.x;
    const size_t base = (size_t)blockIdx.x * 1024;
    const int h  = tid >> 4;       // head (also = g-index of this thread's slice)
    const int d4 = tid & 15;       // float4 index within head dim

    sq4[tid] = *(const float4*)&Q[base + tid * 4];
    sv4[tid] = *(const float4*)&V[base + tid * 4];
    sk4[h * 17 + d4] = *(const float4*)&Kp[base + tid * 4];
    __syncthreads();

    // energy: thread (h, g) with g = d4
    {
        const int gg = d4;
        float e = 0.f;
        #pragma unroll
        for (int q4i = 0; q4i < 16; q4i++) {
            float4 a = sq4[h * 16 + q4i];
            float4 b = sk4[gg * 17 + q4i];
            e += a.x * b.x + a.y * b.y + a.z * b.z + a.w * b.w;
        }
        satt[h][gg] = e * 0.03125f;   // 1/sqrt(1024)
    }
    __syncthreads();

    if (tid < 16) {
        float mx = -1e30f;
        #pragma unroll
        for (int j = 0; j < 16; j++) mx = fmaxf(mx, satt[tid][j]);
        float s = 0.f;
        #pragma unroll
        for (int j = 0; j < 16; j++) {
            float ex = __expf(satt[tid][j] - mx);
            satt[tid][j] = ex; s += ex;
        }
        float inv = 1.f / s;
        #pragma unroll
        for (int j = 0; j < 16; j++) satt[tid][j] *= inv;
    }
    __syncthreads();

    // head mix: this thread owns out[h, d4*4 .. d4*4+3]
    float4 o = make_float4(0.f, 0.f, 0.f, 0.f);
    #pragma unroll
    for (int gg = 0; gg < 16; gg++) {
        const float w = satt[h][gg];
        const float4 vv = sv4[gg * 16 + d4];
        o.x += w * vv.x; o.y += w * vv.y; o.z += w * vv.z; o.w += w * vv.w;
    }
    float s1 = o.x + o.y + o.z + o.w;
    float s2 = o.x * o.x + o.y * o.y + o.z * o.z + o.w * o.w;

    #pragma unroll
    for (int off = 16; off > 0; off >>= 1) {
        s1 += __shfl_xor_sync(0xffffffffu, s1, off);
        s2 += __shfl_xor_sync(0xffffffffu, s2, off);
    }
    const int wid = tid >> 5, lane = tid & 31;
    if (lane == 0) { rbuf[0][wid] = s1; rbuf[1][wid] = s2; }
    __syncthreads();
    if (tid == 0) {
        float t1 = 0.f, t2 = 0.f;
        #pragma unroll
        for (int w = 0; w < 8; w++) { t1 += rbuf[0][w]; t2 += rbuf[1][w]; }
        float mu  = t1 * (1.f / 1024.f);
        float var = t2 * (1.f / 1024.f) - mu * mu;
        rbuf[0][0] = mu;
        rbuf[1][0] = rsqrtf(var + 1e-5f);
    }
    __syncthreads();
    const float mu = rbuf[0][0], rstd = rbuf[1][0];

    const float4 gam = *(const float4*)&lng[tid * 4];
    const float4 bet = *(const float4*)&lnb[tid * 4];
    float4 r;
    r.x = (o.x - mu) * rstd * gam.x + bet.x;
    r.y = (o.y - mu) * rstd * gam.y + bet.y;
    r.z = (o.z - mu) * rstd * gam.z + bet.z;
    r.w = (o.w - mu) * rstd * gam.w + bet.w;
    __half2 h01 = __floats2half2_rn(r.x, r.y);
    __half2 h23 = __floats2half2_rn(r.z, r.w);
    uint2 pk;
    pk.x = *(uint32_t*)&h01;
    pk.y = *(uint32_t*)&h23;
    *(uint2*)&X[base + tid * 4] = pk;
}

// ---------------- launch ----------------
extern "C" void kernel_launch(void* const* d_in, const int* in_sizes, int n_in,
                              void* d_out, int out_size)
{
    const float* query = (const float*)d_in[0];
    const float* key   = (const float*)d_in[1];
    const float* value = (const float*)d_in[2];
    const float* Wq    = (const float*)d_in[3];
    const float* bq    = (const float*)d_in[4];
    const float* Wk    = (const float*)d_in[5];
    const float* bk    = (const float*)d_in[6];
    const float* Wv    = (const float*)d_in[7];
    const float* bv    = (const float*)d_in[8];
    const float* lng   = (const float*)d_in[9];
    const float* lnb   = (const float*)d_in[10];
    const float* Wo    = (const float*)d_in[11];
    const float* bo    = (const float*)d_in[12];
    float* out = (float*)d_out;

    float *pq, *pk, *pv;
    __half *pa, *pw;
    cudaGetSymbolAddress((void**)&pq, g_q);
    cudaGetSymbolAddress((void**)&pk, g_k);
    cudaGetSymbolAddress((void**)&pv, g_v);
    cudaGetSymbolAddress((void**)&pa, g_a16);
    cudaGetSymbolAddress((void**)&pw, g_w16);

    cudaFuncSetAttribute(gemm_mma, cudaFuncAttributeMaxDynamicSharedMemorySize, GEMM_SMEM);

    const int nAct = NTOK_EL;            // 16M
    const int nW   = DMODEL * DMODEL;    // 1M
    dim3 gg(DMODEL / 128, M_TOK / 128);  // (8, 128)

    // Q
    to_f16<<<nAct / 2048, 256>>>(query, pa, nAct);
    to_f16<<<nW / 2048, 256>>>(Wq, pw, nW);
    gemm_mma<<<gg, 256, GEMM_SMEM>>>(pa, pw, bq, pq, DMODEL, DMODEL);
    // K
    to_f16<<<nAct / 2048, 256>>>(key, pa, nAct);
    to_f16<<<nW / 2048, 256>>>(Wk, pw, nW);
    gemm_mma<<<gg, 256, GEMM_SMEM>>>(pa, pw, bk, pk, DMODEL, DMODEL);
    // V
    to_f16<<<nAct / 2048, 256>>>(value, pa, nAct);
    to_f16<<<nW / 2048, 256>>>(Wv, pw, nW);
    gemm_mma<<<gg, 256, GEMM_SMEM>>>(pa, pw, bv, pv, DMODEL, DMODEL);
    // attention + LN -> fp16 X
    attn_ln<<<M_TOK, 256>>>(pq, pk, pv, lng, lnb, pa);
    // output projection
    to_f16<<<nW / 2048, 256>>>(Wo, pw, nW);
    gemm_mma<<<gg, 256, GEMM_SMEM>>>(pa, pw, bo, out, DMODEL, DMODEL);
}

// round 7
// speedup vs baseline: 6.4616x; 1.4583x over previous
#include <cuda_runtime.h>
#include <cuda_fp16.h>
#include <cstdint>

// ---------------------------------------------------------------------------
// Round 7: 64x64 warp tiles (4 warps), 4-stage pipeline, 1 sync per k-block,
//          fp16 Q/K/V intermediates, fused activation converts.
// ---------------------------------------------------------------------------

#define M_TOK   16384
#define DMODEL  1024
#define NTOK_EL (M_TOK * DMODEL)

__device__ __half g_aq[NTOK_EL];      // converted activations (q,k,v inputs)
__device__ __half g_ak[NTOK_EL];
__device__ __half g_av[NTOK_EL];
__device__ __half g_q16[NTOK_EL];     // projection outputs
__device__ __half g_k16[NTOK_EL];
__device__ __half g_v16[NTOK_EL];
__device__ __half g_x16[NTOK_EL];     // attn+LN output
__device__ __half g_w16[DMODEL * DMODEL];

// ---------------- PTX helpers (baseline sm_80-era) ----------------
__device__ __forceinline__ uint32_t smem_u32(const void* p) {
    return (uint32_t)__cvta_generic_to_shared(p);
}
__device__ __forceinline__ void cp16(uint32_t dst, const void* src) {
    asm volatile("cp.async.cg.shared.global [%0], [%1], 16;"
                 :: "r"(dst), "l"(src) : "memory");
}
__device__ __forceinline__ void cp_commit() {
    asm volatile("cp.async.commit_group;" ::: "memory");
}
__device__ __forceinline__ void cp_wait2() {
    asm volatile("cp.async.wait_group 2;" ::: "memory");
}
__device__ __forceinline__ void ldsm4(uint32_t* r, uint32_t addr) {
    asm volatile("ldmatrix.sync.aligned.m8n8.x4.shared.b16 {%0,%1,%2,%3}, [%4];"
                 : "=r"(r[0]), "=r"(r[1]), "=r"(r[2]), "=r"(r[3]) : "r"(addr));
}
__device__ __forceinline__ void mma16816(float* c, const uint32_t* a, const uint32_t* b) {
    asm volatile(
        "mma.sync.aligned.m16n8k16.row.col.f32.f16.f16.f32 "
        "{%0,%1,%2,%3}, {%4,%5,%6,%7}, {%8,%9}, {%0,%1,%2,%3};"
        : "+f"(c[0]), "+f"(c[1]), "+f"(c[2]), "+f"(c[3])
        : "r"(a[0]), "r"(a[1]), "r"(a[2]), "r"(a[3]), "r"(b[0]), "r"(b[1]));
}

// ---------------- converts ----------------
__global__ __launch_bounds__(256)
void to_f16(const float* __restrict__ x, __half* __restrict__ y, int n)
{
    int i = (blockIdx.x * 256 + threadIdx.x) * 8;
    if (i >= n) return;
    float4 v0 = *(const float4*)(x + i);
    float4 v1 = *(const float4*)(x + i + 4);
    __half2 h[4];
    h[0] = __floats2half2_rn(v0.x, v0.y);
    h[1] = __floats2half2_rn(v0.z, v0.w);
    h[2] = __floats2half2_rn(v1.x, v1.y);
    h[3] = __floats2half2_rn(v1.z, v1.w);
    *(uint4*)(y + i) = *(uint4*)h;
}

__global__ __launch_bounds__(256)
void to_f16_3(const float* __restrict__ x0, const float* __restrict__ x1,
              const float* __restrict__ x2, __half* __restrict__ y0,
              __half* __restrict__ y1, __half* __restrict__ y2, int n)
{
    const float* x = (blockIdx.y == 0) ? x0 : (blockIdx.y == 1) ? x1 : x2;
    __half* y      = (blockIdx.y == 0) ? y0 : (blockIdx.y == 1) ? y1 : y2;
    int i = (blockIdx.x * 256 + threadIdx.x) * 8;
    if (i >= n) return;
    float4 v0 = *(const float4*)(x + i);
    float4 v1 = *(const float4*)(x + i + 4);
    __half2 h[4];
    h[0] = __floats2half2_rn(v0.x, v0.y);
    h[1] = __floats2half2_rn(v0.z, v0.w);
    h[2] = __floats2half2_rn(v1.x, v1.y);
    h[3] = __floats2half2_rn(v1.z, v1.w);
    *(uint4*)(y + i) = *(uint4*)h;
}

// ---------------- HMMA GEMM: CTA 128x128, warp 64x64, BK=32, 4 stages -----
#define BK          32
#define MAT_BYTES   8192          // 128 rows * 64B
#define STAGE_BYTES 16384         // A | W
#define STAGES      4
#define GEMM_SMEM   (STAGES * STAGE_BYTES)

__device__ __forceinline__ void load_stage(const __half* A, const __half* W,
                                           int kb, uint32_t sdst,
                                           int tid, int m0, int n0, int K)
{
    #pragma unroll
    for (int i = 0; i < 8; i++) {
        const int id  = i * 128 + tid;
        const int mat = id >> 9;                // 0:A 1:W
        const int idx = id & 511;
        const int row = idx >> 2;
        const int ch  = idx & 3;
        const int grow = ((mat == 0) ? m0 : n0) + row;
        const __half* src = (mat == 0) ? A : W;
        const void* g = src + (size_t)grow * K + kb * BK + ch * 8;
        const uint32_t d = sdst + mat * MAT_BYTES + row * 64
                         + (((uint32_t)(ch ^ ((row >> 1) & 3))) << 4);
        cp16(d, g);
    }
}

template <typename OutT>
__global__ __launch_bounds__(128, 2)
void gemm_mma(const __half* __restrict__ A, const __half* __restrict__ W,
              const float* __restrict__ bias, OutT* __restrict__ C,
              int K, int Ntot)
{
    extern __shared__ char smem[];
    const uint32_t sbase = smem_u32(smem);
    const int tid  = threadIdx.x;
    const int lane = tid & 31;
    const int wid  = tid >> 5;
    const int wm   = wid >> 1;       // 0..1 -> m offset wm*64
    const int wn   = wid & 1;        // 0..1 -> n offset wn*64
    const int m0 = blockIdx.y * 128;
    const int n0 = blockIdx.x * 128;

    const int g = lane >> 3, j = lane & 7;
    const int cA = g >> 1;
    const int rowA_base = wm * 64 + ((g & 1) ? 8 : 0) + j;
    const int cB = g & 1;
    const int rowB_base = wn * 64 + ((g >> 1) ? 8 : 0) + j;

    float acc[4][8][4];
    #pragma unroll
    for (int a = 0; a < 4; a++)
        #pragma unroll
        for (int b = 0; b < 8; b++)
            #pragma unroll
            for (int c = 0; c < 4; c++) acc[a][b][c] = 0.f;

    const int nkb = K / BK;       // 32
    load_stage(A, W, 0, sbase,                   tid, m0, n0, K); cp_commit();
    load_stage(A, W, 1, sbase + STAGE_BYTES,     tid, m0, n0, K); cp_commit();
    load_stage(A, W, 2, sbase + 2 * STAGE_BYTES, tid, m0, n0, K); cp_commit();

    for (int kb = 0; kb < nkb; kb++) {
        cp_wait2();
        __syncthreads();
        if (kb + 3 < nkb)
            load_stage(A, W, kb + 3, sbase + ((kb + 3) & 3) * STAGE_BYTES,
                       tid, m0, n0, K);
        cp_commit();

        const uint32_t st = sbase + (kb & 3) * STAGE_BYTES;
        #pragma unroll
        for (int k16 = 0; k16 < 2; k16++) {
            const int c0 = k16 * 2;
            uint32_t ar[4][4];
            uint32_t bw[16];

            #pragma unroll
            for (int mf = 0; mf < 4; mf++) {
                const int row = rowA_base + mf * 16;
                const uint32_t ad = st + row * 64
                    + (((uint32_t)((c0 + cA) ^ ((row >> 1) & 3))) << 4);
                ldsm4(ar[mf], ad);
            }
            #pragma unroll
            for (int p = 0; p < 4; p++) {
                const int row = rowB_base + p * 16;
                const uint32_t bd = st + MAT_BYTES + row * 64
                    + (((uint32_t)((c0 + cB) ^ ((row >> 1) & 3))) << 4);
                ldsm4(&bw[p * 4], bd);
            }

            #pragma unroll
            for (int mf = 0; mf < 4; mf++)
                #pragma unroll
                for (int nf = 0; nf < 8; nf++)
                    mma16816(acc[mf][nf], ar[mf], &bw[nf * 2]);
        }
    }

    // epilogue
    const int rl = lane >> 2;
    const int cl = (lane & 3) * 2;
    #pragma unroll
    for (int mf = 0; mf < 4; mf++) {
        const int grow = m0 + wm * 64 + mf * 16 + rl;
        #pragma unroll
        for (int nf = 0; nf < 8; nf++) {
            const int gcol = n0 + wn * 64 + nf * 8 + cl;
            const float2 b2 = *(const float2*)&bias[gcol];
            float v0 = acc[mf][nf][0] + b2.x, v1 = acc[mf][nf][1] + b2.y;
            float v2 = acc[mf][nf][2] + b2.x, v3 = acc[mf][nf][3] + b2.y;
            if constexpr (sizeof(OutT) == 4) {
                *(float2*)&C[(size_t)grow * Ntot + gcol]       = make_float2(v0, v1);
                *(float2*)&C[(size_t)(grow + 8) * Ntot + gcol] = make_float2(v2, v3);
            } else {
                *(__half2*)&C[(size_t)grow * Ntot + gcol]       = __floats2half2_rn(v0, v1);
                *(__half2*)&C[(size_t)(grow + 8) * Ntot + gcol] = __floats2half2_rn(v2, v3);
            }
        }
    }
}

// ---------------- per-token head-mix attention + LayerNorm (fp16 I/O) -----
__global__ __launch_bounds__(256)
void attn_ln(const __half* __restrict__ Q, const __half* __restrict__ Kp,
             const __half* __restrict__ V, const float* __restrict__ lng,
             const float* __restrict__ lnb, __half* __restrict__ X)
{
    __shared__ float4 sq4[256];        // [h*16 + d4]
    __shared__ float4 sv4[256];        // [g*16 + d4]
    __shared__ float4 sk4[16 * 17];    // [g*17 + d4] (padded rows)
    __shared__ float  satt[16][17];
    __shared__ float  rbuf[2][8];

    const int tid = threadIdx.x;
    const size_t base = (size_t)blockIdx.x * 1024;
    const int h  = tid >> 4;
    const int d4 = tid & 15;

    auto ld4h = [&](const __half* p) -> float4 {
        uint2 u = *(const uint2*)(p + base + tid * 4);
        float2 a = __half22float2(*(__half2*)&u.x);
        float2 b = __half22float2(*(__half2*)&u.y);
        return make_float4(a.x, a.y, b.x, b.y);
    };
    sq4[tid] = ld4h(Q);
    sv4[tid] = ld4h(V);
    sk4[h * 17 + d4] = ld4h(Kp);
    __syncthreads();

    {
        const int gg = d4;
        float e = 0.f;
        #pragma unroll
        for (int q4i = 0; q4i < 16; q4i++) {
            float4 a = sq4[h * 16 + q4i];
            float4 b = sk4[gg * 17 + q4i];
            e += a.x * b.x + a.y * b.y + a.z * b.z + a.w * b.w;
        }
        satt[h][gg] = e * 0.03125f;   // 1/sqrt(1024)
    }
    __syncthreads();

    if (tid < 16) {
        float mx = -1e30f;
        #pragma unroll
        for (int jj = 0; jj < 16; jj++) mx = fmaxf(mx, satt[tid][jj]);
        float s = 0.f;
        #pragma unroll
        for (int jj = 0; jj < 16; jj++) {
            float ex = __expf(satt[tid][jj] - mx);
            satt[tid][jj] = ex; s += ex;
        }
        float inv = 1.f / s;
        #pragma unroll
        for (int jj = 0; jj < 16; jj++) satt[tid][jj] *= inv;
    }
    __syncthreads();

    float4 o = make_float4(0.f, 0.f, 0.f, 0.f);
    #pragma unroll
    for (int gg = 0; gg < 16; gg++) {
        const float w = satt[h][gg];
        const float4 vv = sv4[gg * 16 + d4];
        o.x += w * vv.x; o.y += w * vv.y; o.z += w * vv.z; o.w += w * vv.w;
    }
    float s1 = o.x + o.y + o.z + o.w;
    float s2 = o.x * o.x + o.y * o.y + o.z * o.z + o.w * o.w;

    #pragma unroll
    for (int off = 16; off > 0; off >>= 1) {
        s1 += __shfl_xor_sync(0xffffffffu, s1, off);
        s2 += __shfl_xor_sync(0xffffffffu, s2, off);
    }
    const int wid = tid >> 5, lane = tid & 31;
    if (lane == 0) { rbuf[0][wid] = s1; rbuf[1][wid] = s2; }
    __syncthreads();
    if (tid == 0) {
        float t1 = 0.f, t2 = 0.f;
        #pragma unroll
        for (int w = 0; w < 8; w++) { t1 += rbuf[0][w]; t2 += rbuf[1][w]; }
        float mu  = t1 * (1.f / 1024.f);
        float var = t2 * (1.f / 1024.f) - mu * mu;
        rbuf[0][0] = mu;
        rbuf[1][0] = rsqrtf(var + 1e-5f);
    }
    __syncthreads();
    const float mu = rbuf[0][0], rstd = rbuf[1][0];

    const float4 gam = *(const float4*)&lng[tid * 4];
    const float4 bet = *(const float4*)&lnb[tid * 4];
    float4 r;
    r.x = (o.x - mu) * rstd * gam.x + bet.x;
    r.y = (o.y - mu) * rstd * gam.y + bet.y;
    r.z = (o.z - mu) * rstd * gam.z + bet.z;
    r.w = (o.w - mu) * rstd * gam.w + bet.w;
    __half2 h01 = __floats2half2_rn(r.x, r.y);
    __half2 h23 = __floats2half2_rn(r.z, r.w);
    uint2 pk;
    pk.x = *(uint32_t*)&h01;
    pk.y = *(uint32_t*)&h23;
    *(uint2*)&X[base + tid * 4] = pk;
}

// ---------------- launch ----------------
extern "C" void kernel_launch(void* const* d_in, const int* in_sizes, int n_in,
                              void* d_out, int out_size)
{
    const float* query = (const float*)d_in[0];
    const float* key   = (const float*)d_in[1];
    const float* value = (const float*)d_in[2];
    const float* Wq    = (const float*)d_in[3];
    const float* bq    = (const float*)d_in[4];
    const float* Wk    = (const float*)d_in[5];
    const float* bk    = (const float*)d_in[6];
    const float* Wv    = (const float*)d_in[7];
    const float* bv    = (const float*)d_in[8];
    const float* lng   = (const float*)d_in[9];
    const float* lnb   = (const float*)d_in[10];
    const float* Wo    = (const float*)d_in[11];
    const float* bo    = (const float*)d_in[12];
    float* out = (float*)d_out;

    __half *paq, *pak, *pav, *pq, *pk, *pv, *px, *pw;
    cudaGetSymbolAddress((void**)&paq, g_aq);
    cudaGetSymbolAddress((void**)&pak, g_ak);
    cudaGetSymbolAddress((void**)&pav, g_av);
    cudaGetSymbolAddress((void**)&pq,  g_q16);
    cudaGetSymbolAddress((void**)&pk,  g_k16);
    cudaGetSymbolAddress((void**)&pv,  g_v16);
    cudaGetSymbolAddress((void**)&px,  g_x16);
    cudaGetSymbolAddress((void**)&pw,  g_w16);

    cudaFuncSetAttribute(gemm_mma<float>,
                         cudaFuncAttributeMaxDynamicSharedMemorySize, GEMM_SMEM);
    cudaFuncSetAttribute(gemm_mma<__half>,
                         cudaFuncAttributeMaxDynamicSharedMemorySize, GEMM_SMEM);

    const int nAct = NTOK_EL;            // 16M
    const int nW   = DMODEL * DMODEL;    // 1M
    dim3 gg(DMODEL / 128, M_TOK / 128);  // (8, 128)
    dim3 cg(nAct / 2048, 3);

    // convert all activations in one launch
    to_f16_3<<<cg, 256>>>(query, key, value, paq, pak, pav, nAct);
    // Q
    to_f16<<<nW / 2048, 256>>>(Wq, pw, nW);
    gemm_mma<__half><<<gg, 128, GEMM_SMEM>>>(paq, pw, bq, pq, DMODEL, DMODEL);
    // K
    to_f16<<<nW / 2048, 256>>>(Wk, pw, nW);
    gemm_mma<__half><<<gg, 128, GEMM_SMEM>>>(pak, pw, bk, pk, DMODEL, DMODEL);
    // V
    to_f16<<<nW / 2048, 256>>>(Wv, pw, nW);
    gemm_mma<__half><<<gg, 128, GEMM_SMEM>>>(pav, pw, bv, pv, DMODEL, DMODEL);
    // attention + LN -> fp16 X
    attn_ln<<<M_TOK, 256>>>(pq, pk, pv, lng, lnb, px);
    // output projection (fp32 out)
    to_f16<<<nW / 2048, 256>>>(Wo, pw, nW);
    gemm_mma<float><<<gg, 128, GEMM_SMEM>>>(px, pw, bo, out, DMODEL, DMODEL);
}

// round 8
// speedup vs baseline: 6.6312x; 1.0263x over previous
#include <cuda_runtime.h>
#include <cuda_fp16.h>
#include <cstdint>

// ---------------------------------------------------------------------------
// Round 8: BK=64 GEMM (halved syncs, 128B-row swizzle), 3-stage cp.async,
//          single fused convert launch for all 7 fp32->fp16 tensors.
// ---------------------------------------------------------------------------

#define M_TOK   16384
#define DMODEL  1024
#define NTOK_EL (M_TOK * DMODEL)
#define NW_EL   (DMODEL * DMODEL)

__device__ __half g_aq[NTOK_EL];
__device__ __half g_ak[NTOK_EL];
__device__ __half g_av[NTOK_EL];
__device__ __half g_q16[NTOK_EL];
__device__ __half g_k16[NTOK_EL];
__device__ __half g_v16[NTOK_EL];
__device__ __half g_x16[NTOK_EL];
__device__ __half g_wq[NW_EL];
__device__ __half g_wk[NW_EL];
__device__ __half g_wv[NW_EL];
__device__ __half g_wo[NW_EL];

// ---------------- PTX helpers (baseline sm_80-era) ----------------
__device__ __forceinline__ uint32_t smem_u32(const void* p) {
    return (uint32_t)__cvta_generic_to_shared(p);
}
__device__ __forceinline__ void cp16(uint32_t dst, const void* src) {
    asm volatile("cp.async.cg.shared.global [%0], [%1], 16;"
                 :: "r"(dst), "l"(src) : "memory");
}
__device__ __forceinline__ void cp_commit() {
    asm volatile("cp.async.commit_group;" ::: "memory");
}
__device__ __forceinline__ void cp_wait1() {
    asm volatile("cp.async.wait_group 1;" ::: "memory");
}
__device__ __forceinline__ void ldsm4(uint32_t* r, uint32_t addr) {
    asm volatile("ldmatrix.sync.aligned.m8n8.x4.shared.b16 {%0,%1,%2,%3}, [%4];"
                 : "=r"(r[0]), "=r"(r[1]), "=r"(r[2]), "=r"(r[3]) : "r"(addr));
}
__device__ __forceinline__ void mma16816(float* c, const uint32_t* a, const uint32_t* b) {
    asm volatile(
        "mma.sync.aligned.m16n8k16.row.col.f32.f16.f16.f32 "
        "{%0,%1,%2,%3}, {%4,%5,%6,%7}, {%8,%9}, {%0,%1,%2,%3};"
        : "+f"(c[0]), "+f"(c[1]), "+f"(c[2]), "+f"(c[3])
        : "r"(a[0]), "r"(a[1]), "r"(a[2]), "r"(a[3]), "r"(b[0]), "r"(b[1]));
}

// ---------------- fused convert: 3 activations + 4 weights ----------------
// grid.x = 3*8192 + 4*512 = 26624 blocks, 256 thr, 8 elems/thread.
#define ACT_BLKS 8192
#define W_BLKS   512

__global__ __launch_bounds__(256)
void conv_all(const float* __restrict__ a0, const float* __restrict__ a1,
              const float* __restrict__ a2,
              const float* __restrict__ w0, const float* __restrict__ w1,
              const float* __restrict__ w2, const float* __restrict__ w3,
              __half* __restrict__ ya0, __half* __restrict__ ya1,
              __half* __restrict__ ya2,
              __half* __restrict__ yw0, __half* __restrict__ yw1,
              __half* __restrict__ yw2, __half* __restrict__ yw3)
{
    int b = blockIdx.x;
    const float* x; __half* y; int blk;
    if (b < 3 * ACT_BLKS) {
        int t = b / ACT_BLKS;
        x = (t == 0) ? a0 : (t == 1) ? a1 : a2;
        y = (t == 0) ? ya0 : (t == 1) ? ya1 : ya2;
        blk = b - t * ACT_BLKS;
    } else {
        int r = b - 3 * ACT_BLKS;
        int t = r / W_BLKS;
        x = (t == 0) ? w0 : (t == 1) ? w1 : (t == 2) ? w2 : w3;
        y = (t == 0) ? yw0 : (t == 1) ? yw1 : (t == 2) ? yw2 : yw3;
        blk = r - t * W_BLKS;
    }
    int i = (blk * 256 + threadIdx.x) * 8;
    float4 v0 = *(const float4*)(x + i);
    float4 v1 = *(const float4*)(x + i + 4);
    __half2 h[4];
    h[0] = __floats2half2_rn(v0.x, v0.y);
    h[1] = __floats2half2_rn(v0.z, v0.w);
    h[2] = __floats2half2_rn(v1.x, v1.y);
    h[3] = __floats2half2_rn(v1.z, v1.w);
    *(uint4*)(y + i) = *(uint4*)h;
}

// ---------------- HMMA GEMM: CTA 128x128, warp 64x64, BK=64, 3 stages -----
// SMEM stage: A | W, each 128 rows x 128B, swizzle chunk c ^= (row & 7).
#define BK          64
#define MAT_BYTES   16384         // 128 rows * 128B
#define STAGE_BYTES 32768         // A | W
#define STAGES      3
#define GEMM_SMEM   (STAGES * STAGE_BYTES)

__device__ __forceinline__ void load_stage(const __half* A, const __half* W,
                                           int kb, uint32_t sdst,
                                           int tid, int m0, int n0, int K)
{
    #pragma unroll
    for (int i = 0; i < 16; i++) {
        const int id  = i * 128 + tid;
        const int mat = id >> 10;               // 0:A 1:W
        const int idx = id & 1023;
        const int row = idx >> 3;
        const int ch  = idx & 7;
        const int grow = ((mat == 0) ? m0 : n0) + row;
        const __half* src = (mat == 0) ? A : W;
        const void* g = src + (size_t)grow * K + kb * BK + ch * 8;
        const uint32_t d = sdst + mat * MAT_BYTES + row * 128
                         + (((uint32_t)(ch ^ (row & 7))) << 4);
        cp16(d, g);
    }
}

template <typename OutT>
__global__ __launch_bounds__(128, 2)
void gemm_mma(const __half* __restrict__ A, const __half* __restrict__ W,
              const float* __restrict__ bias, OutT* __restrict__ C,
              int K, int Ntot)
{
    extern __shared__ char smem[];
    const uint32_t sbase = smem_u32(smem);
    const int tid  = threadIdx.x;
    const int lane = tid & 31;
    const int wid  = tid >> 5;
    const int wm   = wid >> 1;       // 0..1 -> m offset wm*64
    const int wn   = wid & 1;        // 0..1 -> n offset wn*64
    const int m0 = blockIdx.y * 128;
    const int n0 = blockIdx.x * 128;

    const int g = lane >> 3, j = lane & 7;
    const int cA = g >> 1;
    const int rowA_base = wm * 64 + ((g & 1) ? 8 : 0) + j;
    const int cB = g & 1;
    const int rowB_base = wn * 64 + ((g >> 1) ? 8 : 0) + j;

    float acc[4][8][4];
    #pragma unroll
    for (int a = 0; a < 4; a++)
        #pragma unroll
        for (int b = 0; b < 8; b++)
            #pragma unroll
            for (int c = 0; c < 4; c++) acc[a][b][c] = 0.f;

    const int nkb = K / BK;       // 16
    load_stage(A, W, 0, sbase,               tid, m0, n0, K); cp_commit();
    load_stage(A, W, 1, sbase + STAGE_BYTES, tid, m0, n0, K); cp_commit();

    for (int kb = 0; kb < nkb; kb++) {
        cp_wait1();
        __syncthreads();
        if (kb + 2 < nkb)
            load_stage(A, W, kb + 2, sbase + ((kb + 2) % STAGES) * STAGE_BYTES,
                       tid, m0, n0, K);
        cp_commit();

        const uint32_t st = sbase + (kb % STAGES) * STAGE_BYTES;
        #pragma unroll
        for (int k16 = 0; k16 < 4; k16++) {
            const int c0 = k16 * 2;
            uint32_t ar[4][4];
            uint32_t bw[16];

            #pragma unroll
            for (int mf = 0; mf < 4; mf++) {
                const int row = rowA_base + mf * 16;
                const uint32_t ad = st + row * 128
                    + (((uint32_t)((c0 + cA) ^ (row & 7))) << 4);
                ldsm4(ar[mf], ad);
            }
            #pragma unroll
            for (int p = 0; p < 4; p++) {
                const int row = rowB_base + p * 16;
                const uint32_t bd = st + MAT_BYTES + row * 128
                    + (((uint32_t)((c0 + cB) ^ (row & 7))) << 4);
                ldsm4(&bw[p * 4], bd);
            }

            #pragma unroll
            for (int mf = 0; mf < 4; mf++)
                #pragma unroll
                for (int nf = 0; nf < 8; nf++)
                    mma16816(acc[mf][nf], ar[mf], &bw[nf * 2]);
        }
        __syncthreads();
    }

    // epilogue
    const int rl = lane >> 2;
    const int cl = (lane & 3) * 2;
    #pragma unroll
    for (int mf = 0; mf < 4; mf++) {
        const int grow = m0 + wm * 64 + mf * 16 + rl;
        #pragma unroll
        for (int nf = 0; nf < 8; nf++) {
            const int gcol = n0 + wn * 64 + nf * 8 + cl;
            const float2 b2 = *(const float2*)&bias[gcol];
            float v0 = acc[mf][nf][0] + b2.x, v1 = acc[mf][nf][1] + b2.y;
            float v2 = acc[mf][nf][2] + b2.x, v3 = acc[mf][nf][3] + b2.y;
            if constexpr (sizeof(OutT) == 4) {
                *(float2*)&C[(size_t)grow * Ntot + gcol]       = make_float2(v0, v1);
                *(float2*)&C[(size_t)(grow + 8) * Ntot + gcol] = make_float2(v2, v3);
            } else {
                *(__half2*)&C[(size_t)grow * Ntot + gcol]       = __floats2half2_rn(v0, v1);
                *(__half2*)&C[(size_t)(grow + 8) * Ntot + gcol] = __floats2half2_rn(v2, v3);
            }
        }
    }
}

// ---------------- per-token head-mix attention + LayerNorm (fp16 I/O) -----
__global__ __launch_bounds__(256)
void attn_ln(const __half* __restrict__ Q, const __half* __restrict__ Kp,
             const __half* __restrict__ V, const float* __restrict__ lng,
             const float* __restrict__ lnb, __half* __restrict__ X)
{
    __shared__ float4 sq4[256];
    __shared__ float4 sv4[256];
    __shared__ float4 sk4[16 * 17];
    __shared__ float  satt[16][17];
    __shared__ float  rbuf[2][8];

    const int tid = threadIdx.x;
    const size_t base = (size_t)blockIdx.x * 1024;
    const int h  = tid >> 4;
    const int d4 = tid & 15;

    auto ld4h = [&](const __half* p) -> float4 {
        uint2 u = *(const uint2*)(p + base + tid * 4);
        float2 a = __half22float2(*(__half2*)&u.x);
        float2 b = __half22float2(*(__half2*)&u.y);
        return make_float4(a.x, a.y, b.x, b.y);
    };
    sq4[tid] = ld4h(Q);
    sv4[tid] = ld4h(V);
    sk4[h * 17 + d4] = ld4h(Kp);
    __syncthreads();

    {
        const int gg = d4;
        float e = 0.f;
        #pragma unroll
        for (int q4i = 0; q4i < 16; q4i++) {
            float4 a = sq4[h * 16 + q4i];
            float4 b = sk4[gg * 17 + q4i];
            e += a.x * b.x + a.y * b.y + a.z * b.z + a.w * b.w;
        }
        satt[h][gg] = e * 0.03125f;
    }
    __syncthreads();

    if (tid < 16) {
        float mx = -1e30f;
        #pragma unroll
        for (int jj = 0; jj < 16; jj++) mx = fmaxf(mx, satt[tid][jj]);
        float s = 0.f;
        #pragma unroll
        for (int jj = 0; jj < 16; jj++) {
            float ex = __expf(satt[tid][jj] - mx);
            satt[tid][jj] = ex; s += ex;
        }
        float inv = 1.f / s;
        #pragma unroll
        for (int jj = 0; jj < 16; jj++) satt[tid][jj] *= inv;
    }
    __syncthreads();

    float4 o = make_float4(0.f, 0.f, 0.f, 0.f);
    #pragma unroll
    for (int gg = 0; gg < 16; gg++) {
        const float w = satt[h][gg];
        const float4 vv = sv4[gg * 16 + d4];
        o.x += w * vv.x; o.y += w * vv.y; o.z += w * vv.z; o.w += w * vv.w;
    }
    float s1 = o.x + o.y + o.z + o.w;
    float s2 = o.x * o.x + o.y * o.y + o.z * o.z + o.w * o.w;

    #pragma unroll
    for (int off = 16; off > 0; off >>= 1) {
        s1 += __shfl_xor_sync(0xffffffffu, s1, off);
        s2 += __shfl_xor_sync(0xffffffffu, s2, off);
    }
    const int wid = tid >> 5, lane = tid & 31;
    if (lane == 0) { rbuf[0][wid] = s1; rbuf[1][wid] = s2; }
    __syncthreads();
    if (tid == 0) {
        float t1 = 0.f, t2 = 0.f;
        #pragma unroll
        for (int w = 0; w < 8; w++) { t1 += rbuf[0][w]; t2 += rbuf[1][w]; }
        float mu  = t1 * (1.f / 1024.f);
        float var = t2 * (1.f / 1024.f) - mu * mu;
        rbuf[0][0] = mu;
        rbuf[1][0] = rsqrtf(var + 1e-5f);
    }
    __syncthreads();
    const float mu = rbuf[0][0], rstd = rbuf[1][0];

    const float4 gam = *(const float4*)&lng[tid * 4];
    const float4 bet = *(const float4*)&lnb[tid * 4];
    float4 r;
    r.x = (o.x - mu) * rstd * gam.x + bet.x;
    r.y = (o.y - mu) * rstd * gam.y + bet.y;
    r.z = (o.z - mu) * rstd * gam.z + bet.z;
    r.w = (o.w - mu) * rstd * gam.w + bet.w;
    __half2 h01 = __floats2half2_rn(r.x, r.y);
    __half2 h23 = __floats2half2_rn(r.z, r.w);
    uint2 pk;
    pk.x = *(uint32_t*)&h01;
    pk.y = *(uint32_t*)&h23;
    *(uint2*)&X[base + tid * 4] = pk;
}

// ---------------- launch ----------------
extern "C" void kernel_launch(void* const* d_in, const int* in_sizes, int n_in,
                              void* d_out, int out_size)
{
    const float* query = (const float*)d_in[0];
    const float* key   = (const float*)d_in[1];
    const float* value = (const float*)d_in[2];
    const float* Wq    = (const float*)d_in[3];
    const float* bq    = (const float*)d_in[4];
    const float* Wk    = (const float*)d_in[5];
    const float* bk    = (const float*)d_in[6];
    const float* Wv    = (const float*)d_in[7];
    const float* bv    = (const float*)d_in[8];
    const float* lng   = (const float*)d_in[9];
    const float* lnb   = (const float*)d_in[10];
    const float* Wo    = (const float*)d_in[11];
    const float* bo    = (const float*)d_in[12];
    float* out = (float*)d_out;

    __half *paq, *pak, *pav, *pq, *pk, *pv, *px;
    __half *pwq, *pwk, *pwv, *pwo;
    cudaGetSymbolAddress((void**)&paq, g_aq);
    cudaGetSymbolAddress((void**)&pak, g_ak);
    cudaGetSymbolAddress((void**)&pav, g_av);
    cudaGetSymbolAddress((void**)&pq,  g_q16);
    cudaGetSymbolAddress((void**)&pk,  g_k16);
    cudaGetSymbolAddress((void**)&pv,  g_v16);
    cudaGetSymbolAddress((void**)&px,  g_x16);
    cudaGetSymbolAddress((void**)&pwq, g_wq);
    cudaGetSymbolAddress((void**)&pwk, g_wk);
    cudaGetSymbolAddress((void**)&pwv, g_wv);
    cudaGetSymbolAddress((void**)&pwo, g_wo);

    cudaFuncSetAttribute(gemm_mma<float>,
                         cudaFuncAttributeMaxDynamicSharedMemorySize, GEMM_SMEM);
    cudaFuncSetAttribute(gemm_mma<__half>,
                         cudaFuncAttributeMaxDynamicSharedMemorySize, GEMM_SMEM);

    dim3 gg(DMODEL / 128, M_TOK / 128);  // (8, 128)

    // one launch: convert all activations + all weights
    conv_all<<<3 * ACT_BLKS + 4 * W_BLKS, 256>>>(
        query, key, value, Wq, Wk, Wv, Wo,
        paq, pak, pav, pwq, pwk, pwv, pwo);

    gemm_mma<__half><<<gg, 128, GEMM_SMEM>>>(paq, pwq, bq, pq, DMODEL, DMODEL);
    gemm_mma<__half><<<gg, 128, GEMM_SMEM>>>(pak, pwk, bk, pk, DMODEL, DMODEL);
    gemm_mma<__half><<<gg, 128, GEMM_SMEM>>>(pav, pwv, bv, pv, DMODEL, DMODEL);
    attn_ln<<<M_TOK, 256>>>(pq, pk, pv, lng, lnb, px);
    gemm_mma<float><<<gg, 128, GEMM_SMEM>>>(px, pwo, bo, out, DMODEL, DMODEL);
}